// round 1
// baseline (speedup 1.0000x reference)
#include <cuda_runtime.h>

// Combine: out[b, :] = branch[argmax(gate[b, 0..3])][b, :]
// B = 4096 rows, D = 4096 floats per row, N = 4 branches.
// Pure data movement: 64 MB read (selected branch) + 64 MB write.
//
// One block per row. 256 threads/block, each thread copies 4 float4
// (1024 float4 per row). Gate row (4 floats) read redundantly by every
// thread — broadcast hit in L1, negligible.

#define B_ROWS 4096
#define D_DIM  4096
#define THREADS 256
#define F4_PER_ROW (D_DIM / 4)          // 1024
#define F4_PER_THREAD (F4_PER_ROW / THREADS)  // 4

__global__ __launch_bounds__(THREADS)
void combine_select_kernel(const float* __restrict__ b0,
                           const float* __restrict__ b1,
                           const float* __restrict__ b2,
                           const float* __restrict__ b3,
                           const float* __restrict__ gate,
                           float* __restrict__ out) {
    const int row = blockIdx.x;

    // Per-thread argmax over the 4 gate logits (broadcast loads).
    const float g0 = gate[row * 4 + 0];
    const float g1 = gate[row * 4 + 1];
    const float g2 = gate[row * 4 + 2];
    const float g3 = gate[row * 4 + 3];

    // argmax with first-wins tie semantics (matches jnp.argmax).
    int sel = 0;
    float best = g0;
    if (g1 > best) { best = g1; sel = 1; }
    if (g2 > best) { best = g2; sel = 2; }
    if (g3 > best) { best = g3; sel = 3; }

    const float* src;
    switch (sel) {
        case 0:  src = b0; break;
        case 1:  src = b1; break;
        case 2:  src = b2; break;
        default: src = b3; break;
    }

    const float4* src4 = reinterpret_cast<const float4*>(src + (size_t)row * D_DIM);
    float4*       dst4 = reinterpret_cast<float4*>(out + (size_t)row * D_DIM);

    const int t = threadIdx.x;
#pragma unroll
    for (int i = 0; i < F4_PER_THREAD; i++) {
        const int idx = i * THREADS + t;   // coalesced across the block
        dst4[idx] = src4[idx];
    }
}

extern "C" void kernel_launch(void* const* d_in, const int* in_sizes, int n_in,
                              void* d_out, int out_size) {
    const float* b0   = (const float*)d_in[0];
    const float* b1   = (const float*)d_in[1];
    const float* b2   = (const float*)d_in[2];
    const float* b3   = (const float*)d_in[3];
    const float* gate = (const float*)d_in[4];
    float* out = (float*)d_out;

    combine_select_kernel<<<B_ROWS, THREADS>>>(b0, b1, b2, b3, gate, out);
}

// round 2
// speedup vs baseline: 1.0297x; 1.0297x over previous
#include <cuda_runtime.h>

// Combine: out[b, :] = branch[argmax(gate[b, 0..3])][b, :]
// B = 4096 rows, D = 4096 floats per row, N = 4 branches. fp32.
// Pure selection-copy: 64 MB read + 64 MB write minimum.
//
// R2: latency-bound fix. 2 rows per block; gate row loaded as ONE float4;
// 8 independent LDG.128 batched before 8 STG.128 per thread (128 B in
// flight per thread); streaming cache hints (no reuse).

#define B_ROWS 4096
#define D_DIM  4096
#define THREADS 256
#define ROWS_PER_BLOCK 2
#define F4_PER_ROW (D_DIM / 4)                      // 1024
#define F4_PER_THREAD (F4_PER_ROW / THREADS)        // 4 per row

__device__ __forceinline__ const float* pick_branch(
    float4 g, const float* b0, const float* b1,
    const float* b2, const float* b3) {
    // argmax with first-wins tie semantics (matches jnp.argmax).
    const float* src = b0;
    float best = g.x;
    if (g.y > best) { best = g.y; src = b1; }
    if (g.z > best) { best = g.z; src = b2; }
    if (g.w > best) { best = g.w; src = b3; }
    return src;
}

__global__ __launch_bounds__(THREADS)
void combine_select_kernel(const float* __restrict__ b0,
                           const float* __restrict__ b1,
                           const float* __restrict__ b2,
                           const float* __restrict__ b3,
                           const float* __restrict__ gate,
                           float* __restrict__ out) {
    const int row0 = blockIdx.x * ROWS_PER_BLOCK;
    const int row1 = row0 + 1;
    const int t = threadIdx.x;

    // Gate rows are exactly float4-aligned [B,4]: one vector load each.
    const float4 g0 = __ldg(reinterpret_cast<const float4*>(gate) + row0);
    const float4 g1 = __ldg(reinterpret_cast<const float4*>(gate) + row1);

    const float4* src0 = reinterpret_cast<const float4*>(
        pick_branch(g0, b0, b1, b2, b3) + (size_t)row0 * D_DIM);
    const float4* src1 = reinterpret_cast<const float4*>(
        pick_branch(g1, b0, b1, b2, b3) + (size_t)row1 * D_DIM);

    float4* dst0 = reinterpret_cast<float4*>(out + (size_t)row0 * D_DIM);
    float4* dst1 = reinterpret_cast<float4*>(out + (size_t)row1 * D_DIM);

    // Batch all 8 independent loads (evict-first: zero reuse), then stores.
    float4 v[2 * F4_PER_THREAD];
#pragma unroll
    for (int i = 0; i < F4_PER_THREAD; i++)
        v[i] = __ldcs(src0 + i * THREADS + t);
#pragma unroll
    for (int i = 0; i < F4_PER_THREAD; i++)
        v[F4_PER_THREAD + i] = __ldcs(src1 + i * THREADS + t);

#pragma unroll
    for (int i = 0; i < F4_PER_THREAD; i++)
        __stcs(dst0 + i * THREADS + t, v[i]);
#pragma unroll
    for (int i = 0; i < F4_PER_THREAD; i++)
        __stcs(dst1 + i * THREADS + t, v[F4_PER_THREAD + i]);
}

extern "C" void kernel_launch(void* const* d_in, const int* in_sizes, int n_in,
                              void* d_out, int out_size) {
    const float* b0   = (const float*)d_in[0];
    const float* b1   = (const float*)d_in[1];
    const float* b2   = (const float*)d_in[2];
    const float* b3   = (const float*)d_in[3];
    const float* gate = (const float*)d_in[4];
    float* out = (float*)d_out;

    combine_select_kernel<<<B_ROWS / ROWS_PER_BLOCK, THREADS>>>(
        b0, b1, b2, b3, gate, out);
}